// round 1
// baseline (speedup 1.0000x reference)
#include <cuda_runtime.h>
#include <math.h>
#include <stdint.h>

#define SEQ   70
#define BATCH 128
#define HID   512
#define VOCAB 10000

// ---------------- scratch (device globals; no allocation allowed) ----------
__device__ float g_G0[SEQ * BATCH * 3 * HID];   // 8960 x 1536  (55 MB)
__device__ float g_H1[SEQ * BATCH * HID];       // 8960 x 512   (18 MB)
__device__ float g_h0[BATCH * HID];
__device__ float g_h1[BATCH * HID];
__device__ float g_rh[BATCH * HID];
__device__ float g_z [BATCH * HID];
__device__ float g_wh[BATCH * HID];

// ---------------- packed f32x2 helpers (sm_100+ PTX) -----------------------
__device__ __forceinline__ unsigned long long f2pack(float lo, float hi) {
    unsigned long long r;
    asm("mov.b64 %0, {%1, %2};" : "=l"(r) : "f"(lo), "f"(hi));
    return r;
}
__device__ __forceinline__ void f2fma(unsigned long long &c,
                                      unsigned long long a,
                                      unsigned long long b) {
    asm("fma.rn.f32x2 %0, %1, %2, %0;" : "+l"(c) : "l"(a), "l"(b));
}
__device__ __forceinline__ void f2unpack(unsigned long long v, float &lo, float &hi) {
    asm("mov.b64 {%0, %1}, %2;" : "=f"(lo), "=f"(hi) : "l"(v));
}
__device__ __forceinline__ float sigmoidf_(float x) {
    return 1.0f / (1.0f + expf(-x));
}

// ======================================================================
// Big GEMM: C[M,N] = A[M,512] @ B[512,N] + bias   (M = 8960)
// Optional row-gather: A row r = emb[tokens[r]]
// BM=BN=128, BK=16, 256 threads, 8x8 per-thread tile, f32x2 accumulation
// ======================================================================
__global__ __launch_bounds__(256) void sgemm128(
    const float* __restrict__ A, const int* __restrict__ tokens,
    const float* __restrict__ emb,
    const float* __restrict__ B, const float* __restrict__ bias,
    float* __restrict__ C, int N)
{
    __shared__ __align__(16) float As[16][128];   // transposed: As[k][m]
    __shared__ __align__(16) float Bs[16][128];
    __shared__ int toks[128];

    const int tid = threadIdx.x;
    const int bm  = blockIdx.y * 128;
    const int bn  = blockIdx.x * 128;

    if (tokens && tid < 128) toks[tid] = tokens[bm + tid];

    const int ar = tid >> 2;           // 0..63  (rows ar, ar+64)
    const int ak = (tid & 3) << 2;     // 0,4,8,12
    const int br = tid >> 5;           // 0..7   (rows br, br+8)
    const int bc = (tid & 31) << 2;    // 0..124

    const int ty = tid >> 4, tx = tid & 15;
    const int tm = ty * 8,   tn = tx * 8;

    unsigned long long acc[8][4];
#pragma unroll
    for (int m = 0; m < 8; m++)
#pragma unroll
        for (int n = 0; n < 4; n++) acc[m][n] = 0ull;

    __syncthreads();   // toks visible

    for (int k0 = 0; k0 < 512; k0 += 16) {
#pragma unroll
        for (int h = 0; h < 2; h++) {
            int r = ar + h * 64;
            const float* arow = tokens ? (emb + (size_t)toks[r] * 512)
                                       : (A   + (size_t)(bm + r) * 512);
            float4 v = *reinterpret_cast<const float4*>(arow + k0 + ak);
            As[ak + 0][r] = v.x; As[ak + 1][r] = v.y;
            As[ak + 2][r] = v.z; As[ak + 3][r] = v.w;
        }
#pragma unroll
        for (int h = 0; h < 2; h++) {
            int r = br + h * 8;
            float4 v = make_float4(0.f, 0.f, 0.f, 0.f);
            if (bn + bc < N)
                v = *reinterpret_cast<const float4*>(B + (size_t)(k0 + r) * N + bn + bc);
            *reinterpret_cast<float4*>(&Bs[r][bc]) = v;
        }
        __syncthreads();

#pragma unroll
        for (int k = 0; k < 16; k++) {
            float a[8];
            float4 a0 = *reinterpret_cast<const float4*>(&As[k][tm]);
            float4 a1 = *reinterpret_cast<const float4*>(&As[k][tm + 4]);
            a[0] = a0.x; a[1] = a0.y; a[2] = a0.z; a[3] = a0.w;
            a[4] = a1.x; a[5] = a1.y; a[6] = a1.z; a[7] = a1.w;
            unsigned long long b2[4];
            const unsigned long long* bp =
                reinterpret_cast<const unsigned long long*>(&Bs[k][tn]);
            b2[0] = bp[0]; b2[1] = bp[1]; b2[2] = bp[2]; b2[3] = bp[3];
#pragma unroll
            for (int m = 0; m < 8; m++) {
                unsigned long long a2 = f2pack(a[m], a[m]);
#pragma unroll
                for (int n = 0; n < 4; n++) f2fma(acc[m][n], a2, b2[n]);
            }
        }
        __syncthreads();
    }

#pragma unroll
    for (int m = 0; m < 8; m++) {
        int row = bm + tm + m;
#pragma unroll
        for (int n = 0; n < 4; n++) {
            int col = bn + tn + n * 2;
            if (col < N) {   // col,N both even -> col+1 < N too
                float lo, hi; f2unpack(acc[m][n], lo, hi);
                C[(size_t)row * N + col]     = lo + bias[col];
                C[(size_t)row * N + col + 1] = hi + bias[col + 1];
            }
        }
    }
}

// ======================================================================
// Small GEMM body for recurrent phases: 32x64 tile, K=512, 256 threads,
// per-thread 1 row x 8 cols (4 f32x2 accumulators).
// ======================================================================
__device__ __forceinline__ void sg_body(
    const float* __restrict__ A, const float* __restrict__ B, int ldb,
    int bm, int bn, float (*As)[36], float (*Bs)[68],
    unsigned long long acc[4])
{
    const int tid = threadIdx.x;
    const int ar  = tid >> 3;          // 0..31
    const int ak  = (tid & 7) << 2;    // 0..28
    const int bkr = tid >> 3;          // 0..31
    const int bc8 = (tid & 7) << 3;    // 0..56
    const int row = tid >> 3;
    const int c8  = (tid & 7) << 3;

    for (int k0 = 0; k0 < 512; k0 += 32) {
        float4 av = *reinterpret_cast<const float4*>(A + (size_t)(bm + ar) * 512 + k0 + ak);
        *reinterpret_cast<float4*>(&As[ar][ak]) = av;
        float4 b0 = *reinterpret_cast<const float4*>(B + (size_t)(k0 + bkr) * ldb + bn + bc8);
        float4 b1 = *reinterpret_cast<const float4*>(B + (size_t)(k0 + bkr) * ldb + bn + bc8 + 4);
        *reinterpret_cast<float4*>(&Bs[bkr][bc8])     = b0;
        *reinterpret_cast<float4*>(&Bs[bkr][bc8 + 4]) = b1;
        __syncthreads();
#pragma unroll
        for (int k = 0; k < 32; k++) {
            float a = As[row][k];
            unsigned long long a2 = f2pack(a, a);
            const unsigned long long* bp =
                reinterpret_cast<const unsigned long long*>(&Bs[k][c8]);
            f2fma(acc[0], a2, bp[0]);
            f2fma(acc[1], a2, bp[1]);
            f2fma(acc[2], a2, bp[2]);
            f2fma(acc[3], a2, bp[3]);
        }
        __syncthreads();
    }
}

// Phase A: u = h0 @ U_h0 -> r,z of layer0. grid (16,4)
__global__ __launch_bounds__(256) void phaseA(const float* __restrict__ Uh0, int t)
{
    __shared__ __align__(16) float As[32][36];
    __shared__ __align__(16) float Bs[32][68];
    unsigned long long acc[4] = {0ull, 0ull, 0ull, 0ull};
    const int bm = blockIdx.y * 32, bn = blockIdx.x * 64;
    sg_body(g_h0, Uh0, 1024, bm, bn, As, Bs, acc);

    const int tid = threadIdx.x;
    const int b   = bm + (tid >> 3);
    const int c8  = (tid & 7) << 3;
    const float* grow = g_G0 + (size_t)(t * BATCH + b) * 1536;
#pragma unroll
    for (int i = 0; i < 4; i++) {
        float lo, hi; f2unpack(acc[i], lo, hi);
        int j = bn + c8 + 2 * i;
        float s0 = sigmoidf_(grow[j] + lo);
        float s1 = sigmoidf_(grow[j + 1] + hi);
        if (bn < 512) {
            g_rh[b * 512 + j]     = s0 * g_h0[b * 512 + j];
            g_rh[b * 512 + j + 1] = s1 * g_h0[b * 512 + j + 1];
        } else {
            g_z[b * 512 + j - 512] = s0;
            g_z[b * 512 + j - 511] = s1;
        }
    }
}

// Phase B: v = rh @ U_ht0 -> h0 update. grid (8,4)
__global__ __launch_bounds__(256) void phaseB(const float* __restrict__ Uht0, int t)
{
    __shared__ __align__(16) float As[32][36];
    __shared__ __align__(16) float Bs[32][68];
    unsigned long long acc[4] = {0ull, 0ull, 0ull, 0ull};
    const int bm = blockIdx.y * 32, bn = blockIdx.x * 64;
    sg_body(g_rh, Uht0, 512, bm, bn, As, Bs, acc);

    const int tid = threadIdx.x;
    const int b   = bm + (tid >> 3);
    const int c8  = (tid & 7) << 3;
    const float* grow = g_G0 + (size_t)(t * BATCH + b) * 1536;
#pragma unroll
    for (int i = 0; i < 4; i++) {
        float lo, hi; f2unpack(acc[i], lo, hi);
        int j = bn + c8 + 2 * i;
#pragma unroll
        for (int p = 0; p < 2; p++) {
            float v  = p ? hi : lo;
            int   jj = j + p;
            float ht = tanhf(grow[1024 + jj] + v);
            float z  = g_z[b * 512 + jj];
            float h  = g_h0[b * 512 + jj];
            g_h0[b * 512 + jj] = h + z * (ht - h);
        }
    }
}

// Phase C: g1 = h0 @ W_x1 + b1 (+ h1 @ U_h1 for first 1024 cols). grid (24,4)
__global__ __launch_bounds__(256) void phaseC(
    const float* __restrict__ Wx1, const float* __restrict__ Uh1,
    const float* __restrict__ b1, int t)
{
    __shared__ __align__(16) float As[32][36];
    __shared__ __align__(16) float Bs[32][68];
    unsigned long long acc[4] = {0ull, 0ull, 0ull, 0ull};
    const int bm = blockIdx.y * 32, bn = blockIdx.x * 64;
    sg_body(g_h0, Wx1, 1536, bm, bn, As, Bs, acc);
    if (bn < 1024)
        sg_body(g_h1, Uh1, 1024, bm, bn, As, Bs, acc);

    const int tid = threadIdx.x;
    const int b   = bm + (tid >> 3);
    const int c8  = (tid & 7) << 3;
#pragma unroll
    for (int i = 0; i < 4; i++) {
        float lo, hi; f2unpack(acc[i], lo, hi);
        int j = bn + c8 + 2 * i;
        float v0 = lo + b1[j];
        float v1 = hi + b1[j + 1];
        if (bn < 512) {
            float r0 = sigmoidf_(v0), r1 = sigmoidf_(v1);
            g_rh[b * 512 + j]     = r0 * g_h1[b * 512 + j];
            g_rh[b * 512 + j + 1] = r1 * g_h1[b * 512 + j + 1];
        } else if (bn < 1024) {
            g_z[b * 512 + j - 512] = sigmoidf_(v0);
            g_z[b * 512 + j - 511] = sigmoidf_(v1);
        } else {
            g_wh[b * 512 + j - 1024] = v0;
            g_wh[b * 512 + j - 1023] = v1;
        }
    }
}

// Phase D: v = rh1 @ U_ht1 -> h1 update + store into H1 sequence. grid (8,4)
__global__ __launch_bounds__(256) void phaseD(const float* __restrict__ Uht1, int t)
{
    __shared__ __align__(16) float As[32][36];
    __shared__ __align__(16) float Bs[32][68];
    unsigned long long acc[4] = {0ull, 0ull, 0ull, 0ull};
    const int bm = blockIdx.y * 32, bn = blockIdx.x * 64;
    sg_body(g_rh, Uht1, 512, bm, bn, As, Bs, acc);

    const int tid = threadIdx.x;
    const int b   = bm + (tid >> 3);
    const int c8  = (tid & 7) << 3;
#pragma unroll
    for (int i = 0; i < 4; i++) {
        float lo, hi; f2unpack(acc[i], lo, hi);
        int j = bn + c8 + 2 * i;
#pragma unroll
        for (int p = 0; p < 2; p++) {
            float v  = p ? hi : lo;
            int   jj = j + p;
            float ht = tanhf(g_wh[b * 512 + jj] + v);
            float z  = g_z[b * 512 + jj];
            float h  = g_h1[b * 512 + jj];
            float hn = h + z * (ht - h);
            g_h1[b * 512 + jj] = hn;
            g_H1[(size_t)(t * BATCH + b) * 512 + jj] = hn;
        }
    }
}

__global__ void initk(const float* __restrict__ hidden)
{
    int i = blockIdx.x * 256 + threadIdx.x;
    if (i < BATCH * HID) {
        g_h0[i] = hidden[i];
        g_h1[i] = hidden[BATCH * HID + i];
    }
}

__global__ void tailk(float* __restrict__ out)
{
    int i = blockIdx.x * 256 + threadIdx.x;
    if (i < BATCH * HID) {
        out[(size_t)SEQ * BATCH * VOCAB + i]               = g_h0[i];
        out[(size_t)SEQ * BATCH * VOCAB + BATCH * HID + i] = g_h1[i];
    }
}

extern "C" void kernel_launch(void* const* d_in, const int* in_sizes, int n_in,
                              void* d_out, int out_size)
{
    const int*   inputs = (const int*)  d_in[0];
    const float* hidden = (const float*)d_in[1];
    const float* emb    = (const float*)d_in[2];
    const float* Wx0    = (const float*)d_in[3];
    const float* Uh0    = (const float*)d_in[4];
    const float* Uht0   = (const float*)d_in[5];
    const float* b0     = (const float*)d_in[6];
    const float* Wx1    = (const float*)d_in[7];
    const float* Uh1    = (const float*)d_in[8];
    const float* Uht1   = (const float*)d_in[9];
    const float* b1     = (const float*)d_in[10];
    const float* decW   = (const float*)d_in[11];
    const float* decb   = (const float*)d_in[12];
    float* out = (float*)d_out;

    float *G0p = nullptr, *H1p = nullptr;
    cudaGetSymbolAddress((void**)&G0p, g_G0);
    cudaGetSymbolAddress((void**)&H1p, g_H1);

    initk<<<256, 256>>>(hidden);

    // Prologue: G0 = emb[inputs] @ W_x0 + b0   (8960 x 1536)
    sgemm128<<<dim3(12, 70), 256>>>(nullptr, inputs, emb, Wx0, b0, G0p, 1536);

    for (int t = 0; t < SEQ; t++) {
        phaseA<<<dim3(16, 4), 256>>>(Uh0, t);
        phaseB<<<dim3(8, 4), 256>>>(Uht0, t);
        phaseC<<<dim3(24, 4), 256>>>(Wx1, Uh1, b1, t);
        phaseD<<<dim3(8, 4), 256>>>(Uht1, t);
    }

    // Epilogue: logits = H1 @ dec_W + dec_b   (8960 x 10000)
    sgemm128<<<dim3(79, 70), 256>>>(H1p, nullptr, nullptr, decW, decb, out, VOCAB);

    if (out_size >= SEQ * BATCH * VOCAB + 2 * BATCH * HID)
        tailk<<<256, 256>>>(out);
}

// round 2
// speedup vs baseline: 2.3282x; 2.3282x over previous
#include <cuda_runtime.h>
#include <math.h>
#include <stdint.h>

#define SEQ   70
#define BATCH 128
#define HID   512
#define VOCAB 10000
#define NBLK  112
#define ULL   unsigned long long

// ---------------- scratch (device globals; no allocation allowed) ----------
__device__ float g_G0[SEQ * BATCH * 3 * HID];   // 8960 x 1536
__device__ float g_H1[SEQ * BATCH * HID];       // 8960 x 512
__device__ float g_h0[BATCH * HID];
__device__ float g_h1[BATCH * HID];
__device__ float g_rh0[BATCH * HID];
__device__ float g_z0 [BATCH * HID];
__device__ float g_rh1[BATCH * HID];
__device__ float g_z1 [BATCH * HID];
__device__ float g_wh1[BATCH * HID];
__device__ unsigned int g_arrive;
__device__ unsigned int g_gen;

// ---------------- packed f32x2 helpers -------------------------------------
__device__ __forceinline__ ULL f2pack(float lo, float hi) {
    ULL r;
    asm("mov.b64 %0, {%1, %2};" : "=l"(r) : "f"(lo), "f"(hi));
    return r;
}
__device__ __forceinline__ void f2fma(ULL &c, ULL a, ULL b) {
    asm("fma.rn.f32x2 %0, %1, %2, %0;" : "+l"(c) : "l"(a), "l"(b));
}
__device__ __forceinline__ void f2unpack(ULL v, float &lo, float &hi) {
    asm("mov.b64 {%0, %1}, %2;" : "=f"(lo), "=f"(hi) : "l"(v));
}
__device__ __forceinline__ float sigmoidf_(float x) {
    return 1.0f / (1.0f + expf(-x));
}

// ---------------- grid-wide barrier (112 co-resident blocks) ---------------
__device__ __forceinline__ void gridsync(unsigned int &lgen)
{
    __syncthreads();
    if (threadIdx.x == 0) {
        __threadfence();
        unsigned int target = lgen + 1u;
        if (atomicAdd(&g_arrive, 1u) == (unsigned)(NBLK - 1)) {
            g_arrive = 0u;
            __threadfence();
            atomicExch(&g_gen, target);
        } else {
            while (*(volatile unsigned int *)&g_gen != target) { }
        }
        __threadfence();
    }
    __syncthreads();
    lgen += 1u;
}

// ======================================================================
// One GEMM pass: acc(64x32) += A[rowOff.. ,0:512] @ B[0:512, colOff..]
// 128 threads, thread tile 4 rows x 4 cols, register-prefetch pipeline.
// As[k][row] (transposed), Bs[k][col] (pad 36).
// ======================================================================
__device__ void gemm_pass(
    const float* __restrict__ A, int rowOff,
    const float* __restrict__ B, int ldb, int colOff,
    ULL (&acc)[4][2], float (*As)[64], float (*Bs)[36])
{
    const int tid  = threadIdx.x;
    const int arow = tid >> 1;          // 0..63
    const int kh   = (tid & 1) << 4;    // 0 or 16
    const int kr   = tid >> 2;          // 0..31
    const int cq   = (tid & 3) << 2;    // 0,4,8,12
    const int rg   = tid >> 3;          // 0..15
    const int cg   = tid & 7;           // 0..7

    const float* Ap = A + (size_t)(rowOff + arow) * 512 + kh;
    const float* Bp = B + (size_t)kr * ldb + colOff + cq;

    float4 ra0 = *(const float4*)(Ap + 0);
    float4 ra1 = *(const float4*)(Ap + 4);
    float4 ra2 = *(const float4*)(Ap + 8);
    float4 ra3 = *(const float4*)(Ap + 12);
    float4 rb0 = *(const float4*)(Bp);
    float4 rb1 = *(const float4*)(Bp + 16);

#pragma unroll 1
    for (int c = 0; c < 16; ++c) {
        __syncthreads();    // previous chunk's compute done
        As[kh +  0][arow] = ra0.x; As[kh +  1][arow] = ra0.y;
        As[kh +  2][arow] = ra0.z; As[kh +  3][arow] = ra0.w;
        As[kh +  4][arow] = ra1.x; As[kh +  5][arow] = ra1.y;
        As[kh +  6][arow] = ra1.z; As[kh +  7][arow] = ra1.w;
        As[kh +  8][arow] = ra2.x; As[kh +  9][arow] = ra2.y;
        As[kh + 10][arow] = ra2.z; As[kh + 11][arow] = ra2.w;
        As[kh + 12][arow] = ra3.x; As[kh + 13][arow] = ra3.y;
        As[kh + 14][arow] = ra3.z; As[kh + 15][arow] = ra3.w;
        *(float4*)&Bs[kr][cq]      = rb0;
        *(float4*)&Bs[kr][cq + 16] = rb1;
        __syncthreads();
        if (c < 15) {
            Ap += 32;
            Bp += (size_t)32 * ldb;
            ra0 = *(const float4*)(Ap + 0);
            ra1 = *(const float4*)(Ap + 4);
            ra2 = *(const float4*)(Ap + 8);
            ra3 = *(const float4*)(Ap + 12);
            rb0 = *(const float4*)(Bp);
            rb1 = *(const float4*)(Bp + 16);
        }
#pragma unroll
        for (int k = 0; k < 32; ++k) {
            float4 av = *(const float4*)&As[k][rg << 2];
            const ULL* bp2 = (const ULL*)&Bs[k][cg << 2];
            ULL bb0 = bp2[0], bb1 = bp2[1];
            float ar[4] = {av.x, av.y, av.z, av.w};
#pragma unroll
            for (int r = 0; r < 4; ++r) {
                ULL a2 = f2pack(ar[r], ar[r]);
                f2fma(acc[r][0], a2, bb0);
                f2fma(acc[r][1], a2, bb1);
            }
        }
    }
}

__device__ __forceinline__ void run_tile(
    const float* A0, const float* B0, int l0,
    const float* A1, const float* B1, int l1,
    int rowOff, int colOff, ULL (&acc)[4][2],
    float (*As)[64], float (*Bs)[36])
{
    const float* Ap = A0; const float* Bp = B0; int ldb = l0;
    const int np = A1 ? 2 : 1;
#pragma unroll 1
    for (int p = 0; p < np; ++p) {
        gemm_pass(Ap, rowOff, Bp, ldb, colOff, acc, As, Bs);
        Ap = A1; Bp = B1; ldb = l1;
    }
}

// ======================================================================
// Persistent recurrence kernel. 2-layer GRU, layers software-pipelined:
// iteration i handles layer0 step i and layer1 step i-1.
// ======================================================================
__global__ __launch_bounds__(128) void recurrent(
    const float* __restrict__ Uh0,  const float* __restrict__ Uht0,
    const float* __restrict__ Wx1,  const float* __restrict__ Uh1,
    const float* __restrict__ Uht1, const float* __restrict__ b1)
{
    __shared__ __align__(16) float As[32][64];
    __shared__ __align__(16) float Bs[32][36];
    const int bid = blockIdx.x;
    const int tid = threadIdx.x;
    const int rg  = tid >> 3;
    const int cg  = tid & 7;
    unsigned int lgen = 0;

    for (int i = 0; i <= SEQ; ++i) {
        // ------------------ Stage X: gate GEMMs ------------------
        int njobs;
        if (bid < 64)      njobs = (i >= 1)  ? 1 : 0;   // layer1 r/z (double-K)
        else if (bid < 96) njobs = (i < SEQ) ? 2 : 0;   // layer0 r/z
        else               njobs = (i >= 1)  ? 2 : 0;   // layer1 wh

#pragma unroll 1
        for (int it = 0; it < njobs; ++it) {
            int rowOff, colOff, etype;
            const float *A0, *B0, *A1 = nullptr, *B1 = nullptr;
            int l0 = 0, l1 = 0;
            if (bid < 64) {
                colOff = (bid >> 1) << 5;  rowOff = (bid & 1) << 6;
                A0 = g_h0; B0 = Wx1; l0 = 1536;
                A1 = g_h1; B1 = Uh1; l1 = 1024;
                etype = 1;
            } else if (bid < 96) {
                int jj = ((bid - 64) << 1) + it;
                colOff = (jj >> 1) << 5;   rowOff = (jj & 1) << 6;
                A0 = g_h0; B0 = Uh0; l0 = 1024;
                etype = 0;
            } else {
                int jj = ((bid - 96) << 1) + it;
                colOff = 1024 + ((jj >> 1) << 5);  rowOff = (jj & 1) << 6;
                A0 = g_h0; B0 = Wx1; l0 = 1536;
                etype = 2;
            }

            ULL acc[4][2] = {{0ull,0ull},{0ull,0ull},{0ull,0ull},{0ull,0ull}};
            run_tile(A0, B0, l0, A1, B1, l1, rowOff, colOff, acc, As, Bs);

#pragma unroll
            for (int r = 0; r < 4; ++r) {
                int row = rowOff + (rg << 2) + r;
#pragma unroll
                for (int n = 0; n < 2; ++n) {
                    int c = colOff + (cg << 2) + (n << 1);
                    float lo, hi; f2unpack(acc[r][n], lo, hi);
                    if (etype == 0) {
                        const float* G = g_G0 + ((size_t)i * BATCH + row) * 1536;
                        float s0 = sigmoidf_(G[c]     + lo);
                        float s1 = sigmoidf_(G[c + 1] + hi);
                        if (c < 512) {
                            g_rh0[row * 512 + c]     = s0 * g_h0[row * 512 + c];
                            g_rh0[row * 512 + c + 1] = s1 * g_h0[row * 512 + c + 1];
                        } else {
                            g_z0[row * 512 + c - 512] = s0;
                            g_z0[row * 512 + c - 511] = s1;
                        }
                    } else if (etype == 1) {
                        float s0 = sigmoidf_(lo + b1[c]);
                        float s1 = sigmoidf_(hi + b1[c + 1]);
                        if (c < 512) {
                            g_rh1[row * 512 + c]     = s0 * g_h1[row * 512 + c];
                            g_rh1[row * 512 + c + 1] = s1 * g_h1[row * 512 + c + 1];
                        } else {
                            g_z1[row * 512 + c - 512] = s0;
                            g_z1[row * 512 + c - 511] = s1;
                        }
                    } else {
                        g_wh1[row * 512 + c - 1024] = lo + b1[c];
                        g_wh1[row * 512 + c - 1023] = hi + b1[c + 1];
                    }
                }
            }
        }
        gridsync(lgen);

        // ------------------ Stage Y: candidate GEMMs + state update ----
        if (bid < 64) {
            int layer  = bid >> 5;          // 0: layer0, 1: layer1
            int jj     = bid & 31;
            int colOff = (jj >> 1) << 5;    // 0..480
            int rowOff = (jj & 1) << 6;
            bool go = (layer == 0) ? (i < SEQ) : (i >= 1);
            if (go) {
                ULL acc[4][2] = {{0ull,0ull},{0ull,0ull},{0ull,0ull},{0ull,0ull}};
                run_tile(layer == 0 ? g_rh0 : g_rh1,
                         layer == 0 ? Uht0  : Uht1, 512,
                         nullptr, nullptr, 0,
                         rowOff, colOff, acc, As, Bs);
#pragma unroll
                for (int r = 0; r < 4; ++r) {
                    int row = rowOff + (rg << 2) + r;
#pragma unroll
                    for (int n = 0; n < 2; ++n) {
                        int c = colOff + (cg << 2) + (n << 1);
                        float vv[2]; f2unpack(acc[r][n], vv[0], vv[1]);
#pragma unroll
                        for (int p = 0; p < 2; ++p) {
                            int cc  = c + p;
                            int idx = row * 512 + cc;
                            if (layer == 0) {
                                const float* G = g_G0 + ((size_t)i * BATCH + row) * 1536 + 1024;
                                float ht = tanhf(G[cc] + vv[p]);
                                float z  = g_z0[idx];
                                float h  = g_h0[idx];
                                g_h0[idx] = h + z * (ht - h);
                            } else {
                                float ht = tanhf(g_wh1[idx] + vv[p]);
                                float z  = g_z1[idx];
                                float h  = g_h1[idx];
                                float hn = h + z * (ht - h);
                                g_h1[idx] = hn;
                                g_H1[((size_t)(i - 1) * BATCH + row) * 512 + cc] = hn;
                            }
                        }
                    }
                }
            }
        }
        gridsync(lgen);
    }
}

// ======================================================================
// Big GEMM (prologue / decoder), unchanged from round 1 (verified).
// ======================================================================
__global__ __launch_bounds__(256) void sgemm128(
    const float* __restrict__ A, const int* __restrict__ tokens,
    const float* __restrict__ emb,
    const float* __restrict__ B, const float* __restrict__ bias,
    float* __restrict__ C, int N)
{
    __shared__ __align__(16) float As[16][128];
    __shared__ __align__(16) float Bs[16][128];
    __shared__ int toks[128];

    const int tid = threadIdx.x;
    const int bm  = blockIdx.y * 128;
    const int bn  = blockIdx.x * 128;

    if (tokens && tid < 128) toks[tid] = tokens[bm + tid];

    const int ar = tid >> 2;
    const int ak = (tid & 3) << 2;
    const int br = tid >> 5;
    const int bc = (tid & 31) << 2;

    const int ty = tid >> 4, tx = tid & 15;
    const int tm = ty * 8,   tn = tx * 8;

    ULL acc[8][4];
#pragma unroll
    for (int m = 0; m < 8; m++)
#pragma unroll
        for (int n = 0; n < 4; n++) acc[m][n] = 0ull;

    __syncthreads();

    for (int k0 = 0; k0 < 512; k0 += 16) {
#pragma unroll
        for (int h = 0; h < 2; h++) {
            int r = ar + h * 64;
            const float* arow = tokens ? (emb + (size_t)toks[r] * 512)
                                       : (A   + (size_t)(bm + r) * 512);
            float4 v = *reinterpret_cast<const float4*>(arow + k0 + ak);
            As[ak + 0][r] = v.x; As[ak + 1][r] = v.y;
            As[ak + 2][r] = v.z; As[ak + 3][r] = v.w;
        }
#pragma unroll
        for (int h = 0; h < 2; h++) {
            int r = br + h * 8;
            float4 v = make_float4(0.f, 0.f, 0.f, 0.f);
            if (bn + bc < N)
                v = *reinterpret_cast<const float4*>(B + (size_t)(k0 + r) * N + bn + bc);
            *reinterpret_cast<float4*>(&Bs[r][bc]) = v;
        }
        __syncthreads();

#pragma unroll
        for (int k = 0; k < 16; k++) {
            float a[8];
            float4 a0 = *reinterpret_cast<const float4*>(&As[k][tm]);
            float4 a1 = *reinterpret_cast<const float4*>(&As[k][tm + 4]);
            a[0] = a0.x; a[1] = a0.y; a[2] = a0.z; a[3] = a0.w;
            a[4] = a1.x; a[5] = a1.y; a[6] = a1.z; a[7] = a1.w;
            ULL b2[4];
            const ULL* bp = reinterpret_cast<const ULL*>(&Bs[k][tn]);
            b2[0] = bp[0]; b2[1] = bp[1]; b2[2] = bp[2]; b2[3] = bp[3];
#pragma unroll
            for (int m = 0; m < 8; m++) {
                ULL a2 = f2pack(a[m], a[m]);
#pragma unroll
                for (int n = 0; n < 4; n++) f2fma(acc[m][n], a2, b2[n]);
            }
        }
        __syncthreads();
    }

#pragma unroll
    for (int m = 0; m < 8; m++) {
        int row = bm + tm + m;
#pragma unroll
        for (int n = 0; n < 4; n++) {
            int col = bn + tn + n * 2;
            if (col < N) {
                float lo, hi; f2unpack(acc[m][n], lo, hi);
                C[(size_t)row * N + col]     = lo + bias[col];
                C[(size_t)row * N + col + 1] = hi + bias[col + 1];
            }
        }
    }
}

__global__ void initk(const float* __restrict__ hidden)
{
    int i = blockIdx.x * 256 + threadIdx.x;
    if (i == 0) { g_arrive = 0u; g_gen = 0u; }
    if (i < BATCH * HID) {
        g_h0[i] = hidden[i];
        g_h1[i] = hidden[BATCH * HID + i];
    }
}

__global__ void tailk(float* __restrict__ out)
{
    int i = blockIdx.x * 256 + threadIdx.x;
    if (i < BATCH * HID) {
        out[(size_t)SEQ * BATCH * VOCAB + i]               = g_h0[i];
        out[(size_t)SEQ * BATCH * VOCAB + BATCH * HID + i] = g_h1[i];
    }
}

extern "C" void kernel_launch(void* const* d_in, const int* in_sizes, int n_in,
                              void* d_out, int out_size)
{
    const int*   inputs = (const int*)  d_in[0];
    const float* hidden = (const float*)d_in[1];
    const float* emb    = (const float*)d_in[2];
    const float* Wx0    = (const float*)d_in[3];
    const float* Uh0    = (const float*)d_in[4];
    const float* Uht0   = (const float*)d_in[5];
    const float* b0     = (const float*)d_in[6];
    const float* Wx1    = (const float*)d_in[7];
    const float* Uh1    = (const float*)d_in[8];
    const float* Uht1   = (const float*)d_in[9];
    const float* b1     = (const float*)d_in[10];
    const float* decW   = (const float*)d_in[11];
    const float* decb   = (const float*)d_in[12];
    float* out = (float*)d_out;

    float *G0p = nullptr, *H1p = nullptr;
    cudaGetSymbolAddress((void**)&G0p, g_G0);
    cudaGetSymbolAddress((void**)&H1p, g_H1);

    initk<<<256, 256>>>(hidden);

    // Prologue: G0 = emb[inputs] @ W_x0 + b0   (8960 x 1536)
    sgemm128<<<dim3(12, 70), 256>>>(nullptr, inputs, emb, Wx0, b0, G0p, 1536);

    // Persistent 2-layer pipelined recurrence (70 steps, 142 grid barriers)
    recurrent<<<NBLK, 128>>>(Uh0, Uht0, Wx1, Uh1, Uht1, b1);

    // Epilogue: logits = H1 @ dec_W + dec_b   (8960 x 10000)
    sgemm128<<<dim3(79, 70), 256>>>(H1p, nullptr, nullptr, decW, decb, out, VOCAB);

    if (out_size >= SEQ * BATCH * VOCAB + 2 * BATCH * HID)
        tailk<<<256, 256>>>(out);
}

// round 3
// speedup vs baseline: 2.7196x; 1.1681x over previous
#include <cuda_runtime.h>
#include <math.h>
#include <stdint.h>

#define SEQ   70
#define BATCH 128
#define HID   512
#define VOCAB 10000
#define NBLK  112
#define MTOT  (SEQ * BATCH)          // 8960
#define ULL   unsigned long long

// ---------------- scratch (device globals) ---------------------------------
__device__ float g_G0[SEQ * BATCH * 3 * HID];   // 8960 x 1536
__device__ float g_H1T[HID * MTOT];             // [512][8960] transposed
__device__ float g_h0 [BATCH * HID];
__device__ float g_h1A[BATCH * HID];
__device__ float g_h1B[BATCH * HID];
__device__ float g_rh0[BATCH * HID];
__device__ float g_z0 [BATCH * HID];
__device__ float g_g1w[BATCH * 3 * HID];        // raw h0@Wx1
__device__ float g_g1u[BATCH * 2 * HID];        // raw h1@Uh1
__device__ unsigned int g_arrive;
__device__ unsigned int g_gen;

// ---------------- f32x2 helpers --------------------------------------------
__device__ __forceinline__ ULL f2pack(float lo, float hi) {
    ULL r; asm("mov.b64 %0, {%1, %2};" : "=l"(r) : "f"(lo), "f"(hi)); return r;
}
__device__ __forceinline__ void f2fma(ULL &c, ULL a, ULL b) {
    asm("fma.rn.f32x2 %0, %1, %2, %0;" : "+l"(c) : "l"(a), "l"(b));
}
__device__ __forceinline__ void f2unpack(ULL v, float &lo, float &hi) {
    asm("mov.b64 {%0, %1}, %2;" : "=f"(lo), "=f"(hi) : "l"(v));
}
__device__ __forceinline__ float sigmoidf_(float x) {
    return 1.0f / (1.0f + expf(-x));
}

// ---------------- grid barrier (112 co-resident blocks) --------------------
__device__ __forceinline__ void gridsync(unsigned int &lgen)
{
    __syncthreads();
    if (threadIdx.x == 0) {
        __threadfence();
        unsigned int target = lgen + 1u;
        if (atomicAdd(&g_arrive, 1u) == (unsigned)(NBLK - 1)) {
            g_arrive = 0u;
            __threadfence();
            atomicExch(&g_gen, target);
        } else {
            while (*(volatile unsigned int *)&g_gen != target) { }
        }
        __threadfence();
    }
    __syncthreads();
    lgen += 1u;
}

// ======================================================================
// P GEMM: acc(64x64) += A[rowOff..][0:512] @ panel(smem)[0:512][64]
// 256 threads, per-thread 4x4, A staged per 32-K chunk with reg prefetch.
// ======================================================================
__device__ __forceinline__ void gemm_panel64(
    const float* __restrict__ A, int rowOff,
    const float* __restrict__ pP, float* __restrict__ As,
    ULL (&acc)[4][2])
{
    const int tid  = threadIdx.x;
    const int srow = tid >> 2;
    const int skq  = (tid & 3) << 3;
    const int rg   = (tid >> 4) << 2;
    const int cg   = (tid & 15) << 2;

    const float* Ap = A + (size_t)(rowOff + srow) * 512 + skq;
    float4 ra0 = *(const float4*)(Ap);
    float4 ra1 = *(const float4*)(Ap + 4);

#pragma unroll 1
    for (int c = 0; c < 16; ++c) {
        __syncthreads();
        float* as = As + skq * 68 + srow;
        as[0*68]=ra0.x; as[1*68]=ra0.y; as[2*68]=ra0.z; as[3*68]=ra0.w;
        as[4*68]=ra1.x; as[5*68]=ra1.y; as[6*68]=ra1.z; as[7*68]=ra1.w;
        __syncthreads();
        if (c < 15) {
            Ap += 32;
            ra0 = *(const float4*)(Ap);
            ra1 = *(const float4*)(Ap + 4);
        }
        const float* pr = pP + c * 32 * 64 + cg;
#pragma unroll
        for (int k = 0; k < 32; ++k) {
            float4 av = *(const float4*)&As[k * 68 + rg];
            const ULL* bb = (const ULL*)(pr + k * 64);
            ULL b0 = bb[0], b1v = bb[1];
            ULL a0 = f2pack(av.x, av.x);
            ULL a1 = f2pack(av.y, av.y);
            ULL a2 = f2pack(av.z, av.z);
            ULL a3 = f2pack(av.w, av.w);
            f2fma(acc[0][0], a0, b0); f2fma(acc[0][1], a0, b1v);
            f2fma(acc[1][0], a1, b0); f2fma(acc[1][1], a1, b1v);
            f2fma(acc[2][0], a2, b0); f2fma(acc[2][1], a2, b1v);
            f2fma(acc[3][0], a3, b0); f2fma(acc[3][1], a3, b1v);
        }
    }
}

// ======================================================================
// Q GEMM: acc(64x32) += A @ panel(smem)[512][32]. per-thread 4x2.
// ======================================================================
__device__ __forceinline__ void gemm_panel32(
    const float* __restrict__ A, int rowOff,
    const float* __restrict__ pQ, float* __restrict__ As,
    ULL (&acc)[4])
{
    const int tid  = threadIdx.x;
    const int srow = tid >> 2;
    const int skq  = (tid & 3) << 3;
    const int rg   = (tid >> 4) << 2;
    const int cq2  = (tid & 15) << 1;

    const float* Ap = A + (size_t)(rowOff + srow) * 512 + skq;
    float4 ra0 = *(const float4*)(Ap);
    float4 ra1 = *(const float4*)(Ap + 4);

#pragma unroll 1
    for (int c = 0; c < 16; ++c) {
        __syncthreads();
        float* as = As + skq * 68 + srow;
        as[0*68]=ra0.x; as[1*68]=ra0.y; as[2*68]=ra0.z; as[3*68]=ra0.w;
        as[4*68]=ra1.x; as[5*68]=ra1.y; as[6*68]=ra1.z; as[7*68]=ra1.w;
        __syncthreads();
        if (c < 15) {
            Ap += 32;
            ra0 = *(const float4*)(Ap);
            ra1 = *(const float4*)(Ap + 4);
        }
        const float* pr = pQ + c * 32 * 32 + cq2;
#pragma unroll
        for (int k = 0; k < 32; ++k) {
            float4 av = *(const float4*)&As[k * 68 + rg];
            ULL b0 = *(const ULL*)(pr + k * 32);
            f2fma(acc[0], f2pack(av.x, av.x), b0);
            f2fma(acc[1], f2pack(av.y, av.y), b0);
            f2fma(acc[2], f2pack(av.z, av.z), b0);
            f2fma(acc[3], f2pack(av.w, av.w), b0);
        }
    }
}

// rh1 on-the-fly: rh = sigmoid(g1w + g1u + b1) * h1_prev  (8 consecutive cols)
__device__ __forceinline__ void load_rh1(
    const float* wp, const float* up, const float* hp, const float* bp,
    float rh[8])
{
    float4 w0=*(const float4*)wp,     w1=*(const float4*)(wp+4);
    float4 u0=*(const float4*)up,     u1=*(const float4*)(up+4);
    float4 h0v=*(const float4*)hp,    h1v=*(const float4*)(hp+4);
    float4 b0=*(const float4*)bp,     b1v=*(const float4*)(bp+4);
    rh[0]=sigmoidf_(w0.x+u0.x+b0.x)*h0v.x;
    rh[1]=sigmoidf_(w0.y+u0.y+b0.y)*h0v.y;
    rh[2]=sigmoidf_(w0.z+u0.z+b0.z)*h0v.z;
    rh[3]=sigmoidf_(w0.w+u0.w+b0.w)*h0v.w;
    rh[4]=sigmoidf_(w1.x+u1.x+b1v.x)*h1v.x;
    rh[5]=sigmoidf_(w1.y+u1.y+b1v.y)*h1v.y;
    rh[6]=sigmoidf_(w1.z+u1.z+b1v.z)*h1v.z;
    rh[7]=sigmoidf_(w1.w+u1.w+b1v.w)*h1v.w;
}

// Q GEMM with A = rh1 computed on the fly (layer-1 candidate)
__device__ __forceinline__ void gemm_panel32_rh1(
    int rowOff, const float* __restrict__ pQ, float* __restrict__ As,
    const float* __restrict__ h1rd, const float* __restrict__ b1,
    ULL (&acc)[4])
{
    const int tid  = threadIdx.x;
    const int srow = tid >> 2;
    const int skq  = (tid & 3) << 3;
    const int rg   = (tid >> 4) << 2;
    const int cq2  = (tid & 15) << 1;

    const float* wp = g_g1w + (size_t)(rowOff + srow) * 1536 + skq;
    const float* up = g_g1u + (size_t)(rowOff + srow) * 1024 + skq;
    const float* hp = h1rd  + (size_t)(rowOff + srow) * 512  + skq;
    const float* bp = b1 + skq;

    float rh[8];
    load_rh1(wp, up, hp, bp, rh);

#pragma unroll 1
    for (int c = 0; c < 16; ++c) {
        __syncthreads();
        float* as = As + skq * 68 + srow;
#pragma unroll
        for (int j = 0; j < 8; ++j) as[j*68] = rh[j];
        __syncthreads();
        if (c < 15) {
            load_rh1(wp + (c+1)*32, up + (c+1)*32, hp + (c+1)*32,
                     bp + (c+1)*32, rh);
        }
        const float* pr = pQ + c * 32 * 32 + cq2;
#pragma unroll
        for (int k = 0; k < 32; ++k) {
            float4 av = *(const float4*)&As[k * 68 + rg];
            ULL b0 = *(const ULL*)(pr + k * 32);
            f2fma(acc[0], f2pack(av.x, av.x), b0);
            f2fma(acc[1], f2pack(av.y, av.y), b0);
            f2fma(acc[2], f2pack(av.z, av.z), b0);
            f2fma(acc[3], f2pack(av.w, av.w), b0);
        }
    }
}

// ======================================================================
// Persistent recurrence kernel: SMEM-resident weight panels,
// 2 grid barriers / iteration, layers software-pipelined.
// ======================================================================
__global__ __launch_bounds__(256) void recurrent(
    const float* __restrict__ Uh0,  const float* __restrict__ Uht0,
    const float* __restrict__ Wx1,  const float* __restrict__ Uh1,
    const float* __restrict__ Uht1, const float* __restrict__ b1)
{
    extern __shared__ float sm[];
    float* pP = sm;              // 512*64 = 32768 floats
    float* pQ = sm + 32768;      // 512*32 = 16384 floats
    float* As = sm + 49152;      // 32*68  =  2176 floats

    const int bid = blockIdx.x;
    const int tid = threadIdx.x;
    const int rg  = (tid >> 4) << 2;
    const int cg  = (tid & 15) << 2;
    const int cq2 = (tid & 15) << 1;

    // ---- role assignment -------------------------------------------------
    int ptype, ProwOff, PcolOff, Pldb;
    const float* PB;
    if (bid < 32)      { ptype=0; PB=Uh0; Pldb=1024; PcolOff=(bid>>1)<<6;      ProwOff=(bid&1)<<6; }
    else if (bid < 80) { ptype=1; PB=Wx1; Pldb=1536; PcolOff=((bid-32)>>1)<<6; ProwOff=((bid-32)&1)<<6; }
    else               { ptype=2; PB=Uh1; Pldb=1024; PcolOff=((bid-80)>>1)<<6; ProwOff=((bid-80)&1)<<6; }

    int QrowOff = 0, QcolOff = 0;
    const float* QB = nullptr;
    if (bid < 64) {
        int q = bid & 31;
        QB = (bid < 32) ? Uht0 : Uht1;
        QcolOff = (q >> 1) << 5;
        QrowOff = (q & 1) << 6;
    }

    // ---- one-time panel loads -------------------------------------------
    for (int j = tid; j < 8192; j += 256) {            // 512 x 16 float4
        int k = j >> 4, q = j & 15;
        *(float4*)&pP[k*64 + q*4] =
            *(const float4*)&PB[(size_t)k * Pldb + PcolOff + q*4];
    }
    if (QB) {
        for (int j = tid; j < 4096; j += 256) {        // 512 x 8 float4
            int k = j >> 3, q = j & 7;
            *(float4*)&pQ[k*32 + q*4] =
                *(const float4*)&QB[(size_t)k * 512 + QcolOff + q*4];
        }
    }
    __syncthreads();

    unsigned int lgen = 0;

    for (int i = 0; i <= SEQ; ++i) {
        const bool l0 = (i < SEQ), l1 = (i >= 1);
        const float* h1rd = (i & 1) ? g_h1B : g_h1A;
        float*       h1wr = ((i + 1) & 1) ? g_h1B : g_h1A;

        // ---------------- stage P: gate GEMMs ----------------
        if (ptype == 0 ? l0 : l1) {
            ULL acc[4][2] = {{0ull,0ull},{0ull,0ull},{0ull,0ull},{0ull,0ull}};
            const float* A = (ptype == 2) ? h1rd : g_h0;
            gemm_panel64(A, ProwOff, pP, As, acc);

#pragma unroll
            for (int r = 0; r < 4; ++r) {
                int row = ProwOff + rg + r;
#pragma unroll
                for (int n = 0; n < 2; ++n) {
                    int col = PcolOff + cg + (n << 1);
                    float lo, hi; f2unpack(acc[r][n], lo, hi);
                    if (ptype == 0) {
                        const float* G = g_G0 + ((size_t)i * BATCH + row) * 1536;
                        float s0 = sigmoidf_(G[col]     + lo);
                        float s1 = sigmoidf_(G[col + 1] + hi);
                        if (col < 512) {
                            g_rh0[row*512 + col]     = s0 * g_h0[row*512 + col];
                            g_rh0[row*512 + col + 1] = s1 * g_h0[row*512 + col + 1];
                        } else {
                            g_z0[row*512 + col - 512] = s0;
                            g_z0[row*512 + col - 511] = s1;
                        }
                    } else if (ptype == 1) {
                        *(float2*)&g_g1w[(size_t)row*1536 + col] = make_float2(lo, hi);
                    } else {
                        *(float2*)&g_g1u[(size_t)row*1024 + col] = make_float2(lo, hi);
                    }
                }
            }
        }
        gridsync(lgen);

        // ---------------- stage Q: candidate GEMMs + state update ------
        if (bid < 32) {
            if (l0) {
                ULL acc[4] = {0ull,0ull,0ull,0ull};
                gemm_panel32(g_rh0, QrowOff, pQ, As, acc);
#pragma unroll
                for (int r = 0; r < 4; ++r) {
                    int row = QrowOff + rg + r;
                    const float* G = g_G0 + ((size_t)i * BATCH + row) * 1536 + 1024;
                    float vv[2]; f2unpack(acc[r], vv[0], vv[1]);
#pragma unroll
                    for (int p = 0; p < 2; ++p) {
                        int cc  = QcolOff + cq2 + p;
                        int idx = row * 512 + cc;
                        float ht = tanhf(G[cc] + vv[p]);
                        float z  = g_z0[idx];
                        float h  = g_h0[idx];
                        g_h0[idx] = h + z * (ht - h);
                    }
                }
            }
        } else if (bid < 64) {
            if (l1) {
                ULL acc[4] = {0ull,0ull,0ull,0ull};
                gemm_panel32_rh1(QrowOff, pQ, As, h1rd, b1, acc);
                const float* b1w = b1 + 1024;
                const float* b1z = b1 + 512;
#pragma unroll
                for (int r = 0; r < 4; ++r) {
                    int row = QrowOff + rg + r;
                    float vv[2]; f2unpack(acc[r], vv[0], vv[1]);
#pragma unroll
                    for (int p = 0; p < 2; ++p) {
                        int cc  = QcolOff + cq2 + p;
                        int idx = row * 512 + cc;
                        float w  = g_g1w[(size_t)row*1536 + 1024 + cc] + b1w[cc];
                        float ht = tanhf(w + vv[p]);
                        float zz = sigmoidf_(g_g1w[(size_t)row*1536 + 512 + cc]
                                           + g_g1u[(size_t)row*1024 + 512 + cc]
                                           + b1z[cc]);
                        float h  = h1rd[idx];
                        float hn = h + zz * (ht - h);
                        h1wr[idx] = hn;
                        g_H1T[(size_t)cc * MTOT + (size_t)(i - 1) * BATCH + row] = hn;
                    }
                }
            }
        }
        gridsync(lgen);
    }
}

// ======================================================================
// Big GEMM (prologue, with token gather) — verified in R1/R2.
// ======================================================================
__global__ __launch_bounds__(256) void sgemm128(
    const float* __restrict__ A, const int* __restrict__ tokens,
    const float* __restrict__ emb,
    const float* __restrict__ B, const float* __restrict__ bias,
    float* __restrict__ C, int N)
{
    __shared__ __align__(16) float As[16][128];
    __shared__ __align__(16) float Bs[16][128];
    __shared__ int toks[128];

    const int tid = threadIdx.x;
    const int bm  = blockIdx.y * 128;
    const int bn  = blockIdx.x * 128;

    if (tokens && tid < 128) toks[tid] = tokens[bm + tid];

    const int ar = tid >> 2;
    const int ak = (tid & 3) << 2;
    const int br = tid >> 5;
    const int bc = (tid & 31) << 2;
    const int ty = tid >> 4, tx = tid & 15;
    const int tm = ty * 8,   tn = tx * 8;

    ULL acc[8][4];
#pragma unroll
    for (int m = 0; m < 8; m++)
#pragma unroll
        for (int n = 0; n < 4; n++) acc[m][n] = 0ull;

    __syncthreads();

    for (int k0 = 0; k0 < 512; k0 += 16) {
#pragma unroll
        for (int h = 0; h < 2; h++) {
            int r = ar + h * 64;
            const float* arow = tokens ? (emb + (size_t)toks[r] * 512)
                                       : (A   + (size_t)(bm + r) * 512);
            float4 v = *reinterpret_cast<const float4*>(arow + k0 + ak);
            As[ak + 0][r] = v.x; As[ak + 1][r] = v.y;
            As[ak + 2][r] = v.z; As[ak + 3][r] = v.w;
        }
#pragma unroll
        for (int h = 0; h < 2; h++) {
            int r = br + h * 8;
            float4 v = make_float4(0.f, 0.f, 0.f, 0.f);
            if (bn + bc < N)
                v = *reinterpret_cast<const float4*>(B + (size_t)(k0 + r) * N + bn + bc);
            *reinterpret_cast<float4*>(&Bs[r][bc]) = v;
        }
        __syncthreads();

#pragma unroll
        for (int k = 0; k < 16; k++) {
            float a[8];
            float4 a0 = *reinterpret_cast<const float4*>(&As[k][tm]);
            float4 a1 = *reinterpret_cast<const float4*>(&As[k][tm + 4]);
            a[0] = a0.x; a[1] = a0.y; a[2] = a0.z; a[3] = a0.w;
            a[4] = a1.x; a[5] = a1.y; a[6] = a1.z; a[7] = a1.w;
            ULL b2[4];
            const ULL* bp = reinterpret_cast<const ULL*>(&Bs[k][tn]);
            b2[0] = bp[0]; b2[1] = bp[1]; b2[2] = bp[2]; b2[3] = bp[3];
#pragma unroll
            for (int m = 0; m < 8; m++) {
                ULL a2 = f2pack(a[m], a[m]);
#pragma unroll
                for (int n = 0; n < 4; n++) f2fma(acc[m][n], a2, b2[n]);
            }
        }
        __syncthreads();
    }

#pragma unroll
    for (int m = 0; m < 8; m++) {
        int row = bm + tm + m;
#pragma unroll
        for (int n = 0; n < 4; n++) {
            int col = bn + tn + n * 2;
            if (col < N) {
                float lo, hi; f2unpack(acc[m][n], lo, hi);
                C[(size_t)row * N + col]     = lo + bias[col];
                C[(size_t)row * N + col + 1] = hi + bias[col + 1];
            }
        }
    }
}

// ======================================================================
// Decoder GEMM: A transposed [512][8960] -> fully vectorized staging.
// ======================================================================
__global__ __launch_bounds__(256) void sgemm128T(
    const float* __restrict__ AT,
    const float* __restrict__ B, const float* __restrict__ bias,
    float* __restrict__ C, int N)
{
    __shared__ __align__(16) float As[16][128];
    __shared__ __align__(16) float Bs[16][128];

    const int tid = threadIdx.x;
    const int bm  = blockIdx.y * 128;
    const int bn  = blockIdx.x * 128;

    const int tk  = tid >> 4;           // 0..15
    const int tml = (tid & 15) << 3;    // 0..120
    const int br  = tid >> 5;           // 0..7
    const int bc  = (tid & 31) << 2;    // 0..124
    const int ty = tid >> 4, tx = tid & 15;
    const int tm = ty * 8,   tn = tx * 8;
    const bool bok = (bn + bc < N);

    ULL acc[8][4];
#pragma unroll
    for (int m = 0; m < 8; m++)
#pragma unroll
        for (int n = 0; n < 4; n++) acc[m][n] = 0ull;

    const float* Ap = AT + (size_t)tk * MTOT + bm + tml;
    const float* Bp = B  + (size_t)br * N + bn + bc;

    float4 pa0 = *(const float4*)(Ap);
    float4 pa1 = *(const float4*)(Ap + 4);
    float4 pb0 = bok ? *(const float4*)(Bp)               : make_float4(0,0,0,0);
    float4 pb1 = bok ? *(const float4*)(Bp + (size_t)8*N) : make_float4(0,0,0,0);

#pragma unroll 1
    for (int k0 = 0; k0 < 512; k0 += 16) {
        __syncthreads();
        *(float4*)&As[tk][tml]     = pa0;
        *(float4*)&As[tk][tml + 4] = pa1;
        *(float4*)&Bs[br][bc]      = pb0;
        *(float4*)&Bs[br + 8][bc]  = pb1;
        __syncthreads();
        if (k0 < 496) {
            Ap += (size_t)16 * MTOT;
            Bp += (size_t)16 * N;
            pa0 = *(const float4*)(Ap);
            pa1 = *(const float4*)(Ap + 4);
            pb0 = bok ? *(const float4*)(Bp)               : make_float4(0,0,0,0);
            pb1 = bok ? *(const float4*)(Bp + (size_t)8*N) : make_float4(0,0,0,0);
        }
#pragma unroll
        for (int k = 0; k < 16; k++) {
            float4 a0 = *(const float4*)&As[k][tm];
            float4 a1 = *(const float4*)&As[k][tm + 4];
            float a[8] = {a0.x,a0.y,a0.z,a0.w,a1.x,a1.y,a1.z,a1.w};
            ULL b2[4];
            const ULL* bp = (const ULL*)&Bs[k][tn];
            b2[0] = bp[0]; b2[1] = bp[1]; b2[2] = bp[2]; b2[3] = bp[3];
#pragma unroll
            for (int m = 0; m < 8; m++) {
                ULL a2 = f2pack(a[m], a[m]);
#pragma unroll
                for (int n = 0; n < 4; n++) f2fma(acc[m][n], a2, b2[n]);
            }
        }
    }

#pragma unroll
    for (int m = 0; m < 8; m++) {
        int row = bm + tm + m;
#pragma unroll
        for (int n = 0; n < 4; n++) {
            int col = bn + tn + n * 2;
            if (col < N) {
                float lo, hi; f2unpack(acc[m][n], lo, hi);
                C[(size_t)row * N + col]     = lo + bias[col];
                C[(size_t)row * N + col + 1] = hi + bias[col + 1];
            }
        }
    }
}

__global__ void initk(const float* __restrict__ hidden)
{
    int i = blockIdx.x * 256 + threadIdx.x;
    if (i == 0) { g_arrive = 0u; g_gen = 0u; }
    if (i < BATCH * HID) {
        g_h0 [i] = hidden[i];
        g_h1B[i] = hidden[BATCH * HID + i];
    }
}

__global__ void tailk(float* __restrict__ out)
{
    int i = blockIdx.x * 256 + threadIdx.x;
    if (i < BATCH * HID) {
        out[(size_t)SEQ * BATCH * VOCAB + i]               = g_h0[i];
        out[(size_t)SEQ * BATCH * VOCAB + BATCH * HID + i] = g_h1B[i];
    }
}

extern "C" void kernel_launch(void* const* d_in, const int* in_sizes, int n_in,
                              void* d_out, int out_size)
{
    const int*   inputs = (const int*)  d_in[0];
    const float* hidden = (const float*)d_in[1];
    const float* emb    = (const float*)d_in[2];
    const float* Wx0    = (const float*)d_in[3];
    const float* Uh0    = (const float*)d_in[4];
    const float* Uht0   = (const float*)d_in[5];
    const float* b0     = (const float*)d_in[6];
    const float* Wx1    = (const float*)d_in[7];
    const float* Uh1    = (const float*)d_in[8];
    const float* Uht1   = (const float*)d_in[9];
    const float* b1     = (const float*)d_in[10];
    const float* decW   = (const float*)d_in[11];
    const float* decb   = (const float*)d_in[12];
    float* out = (float*)d_out;

    float *G0p = nullptr, *H1Tp = nullptr;
    cudaGetSymbolAddress((void**)&G0p,  g_G0);
    cudaGetSymbolAddress((void**)&H1Tp, g_H1T);

    const int SMEM_REC = (32768 + 16384 + 32 * 68) * 4;   // 205312 B
    cudaFuncSetAttribute(recurrent,
        cudaFuncAttributeMaxDynamicSharedMemorySize, SMEM_REC);

    initk<<<256, 256>>>(hidden);

    // Prologue: G0 = emb[inputs] @ W_x0 + b0   (8960 x 1536)
    sgemm128<<<dim3(12, 70), 256>>>(nullptr, inputs, emb, Wx0, b0, G0p, 1536);

    // Persistent recurrence: SMEM-resident weights, 142 grid barriers
    recurrent<<<NBLK, 256, SMEM_REC>>>(Uh0, Uht0, Wx1, Uh1, Uht1, b1);

    // Epilogue: logits = H1T^T @ dec_W + dec_b   (8960 x 10000)
    sgemm128T<<<dim3(79, 70), 256>>>(H1Tp, decW, decb, out, VOCAB);

    if (out_size >= SEQ * BATCH * VOCAB + 2 * BATCH * HID)
        tailk<<<256, 256>>>(out);
}